// round 10
// baseline (speedup 1.0000x reference)
#include <cuda_runtime.h>
#include <cuda_bf16.h>
#include <math.h>

typedef unsigned int u32;
typedef unsigned short u16;
typedef unsigned char u8;
typedef unsigned long long u64;
typedef unsigned long long ull;

#define N_SEQ 4096
#define M_SEQ 1024
#define DIMC  512
#define INNER 512
#define HEADS 8
#define GROUPS 8

// ---------------- helpers ------------------------------------------------------
__device__ __forceinline__ u32 smem_u32(const void* p) {
    u32 a;
    asm("{ .reg .u64 t; cvta.to.shared.u64 t, %1; cvt.u32.u64 %0, t; }" : "=r"(a) : "l"(p));
    return a;
}
__device__ __forceinline__ float ex2f(float x) {
    float r; asm("ex2.approx.ftz.f32 %0, %1;" : "=f"(r) : "f"(x)); return r;
}
__device__ __forceinline__ void ldsm_x4(u32 addr, u32& r0, u32& r1, u32& r2, u32& r3) {
    asm volatile("ldmatrix.sync.aligned.m8n8.x4.shared.b16 {%0,%1,%2,%3}, [%4];"
        : "=r"(r0), "=r"(r1), "=r"(r2), "=r"(r3) : "r"(addr));
}
__device__ __forceinline__ void ldsm_x2(u32 addr, u32& r0, u32& r1) {
    asm volatile("ldmatrix.sync.aligned.m8n8.x2.shared.b16 {%0,%1}, [%2];"
        : "=r"(r0), "=r"(r1) : "r"(addr));
}
__device__ __forceinline__ void mma16816(float* c, u32 a0, u32 a1, u32 a2, u32 a3,
                                         u32 b0, u32 b1) {
    asm volatile(
        "mma.sync.aligned.m16n8k16.row.col.f32.bf16.bf16.f32 "
        "{%0,%1,%2,%3}, {%4,%5,%6,%7}, {%8,%9}, {%0,%1,%2,%3};"
        : "+f"(c[0]), "+f"(c[1]), "+f"(c[2]), "+f"(c[3])
        : "r"(a0), "r"(a1), "r"(a2), "r"(a3), "r"(b0), "r"(b1));
}
// int8 MMA k=32 (sm_80+, no arch suffix): exact s32 accumulation
__device__ __forceinline__ void mma_s8(int* c, const u32* a, u32 b0, u32 b1) {
    asm volatile(
        "mma.sync.aligned.m16n8k32.row.col.s32.s8.s8.s32 "
        "{%0,%1,%2,%3}, {%4,%5,%6,%7}, {%8,%9}, {%0,%1,%2,%3};"
        : "+r"(c[0]), "+r"(c[1]), "+r"(c[2]), "+r"(c[3])
        : "r"(a[0]), "r"(a[1]), "r"(a[2]), "r"(a[3]), "r"(b0), "r"(b1));
}
__device__ __forceinline__ u32 pack_bf16(float a, float b) {
    return ((u32)__bfloat16_as_ushort(__float2bfloat16(b)) << 16) |
           (u32)__bfloat16_as_ushort(__float2bfloat16(a));
}
__device__ __forceinline__ float bfhi(float x) {
    return __bfloat162float(__float2bfloat16(x));
}
__device__ __forceinline__ u16 pk2s8(float a, float b) {
    int ia = (int)rintf(a), ib = (int)rintf(b);
    return (u16)((ia & 0xff) | ((ib & 0xff) << 8));
}
__device__ __forceinline__ void cp_async16(u32 s, const void* g) {
    asm volatile("cp.async.cg.shared.global [%0], [%1], 16;" :: "r"(s), "l"(g));
}
#define CP_COMMIT() asm volatile("cp.async.commit_group;" ::: "memory")
#define CP_WAIT(n)  asm volatile("cp.async.wait_group %0;" :: "n"(n) : "memory")

// ---------------- scratch ------------------------------------------------------
__device__ float g_qT[N_SEQ * DIMC];              // q[i][c] fp32
__device__ float g_pos[GROUPS * M_SEQ];
__device__ u8    g_kq[2 * M_SEQ * 1024];          // int8 K [s][t][h*128: a1 x64 | a0 x64]
__device__ float g_ksc[2 * HEADS * M_SEQ];        // K row scale [s][h][t]
__device__ float g_vf[2 * M_SEQ * INNER];         // V fp32 [s][t][c]
__device__ u32   g_vmax[2 * INNER];               // per-(s,ch) |v| max (float bits)
__device__ u8    g_vq[2 * INNER * 32 * 64];       // int8 V [s][ch][jchunk][b1 x32 | b0 x32]
__device__ float g_vsc[2 * INNER];                // V channel scale
__device__ float g_att[2 * N_SEQ * INNER];        // attn out [s][i][c]

#define SMSTRIDE 144
#define QSCL 0.1803368801111204f   // 0.125 * log2(e)

// ================= Kernel 0: zero vmax (graph-safe re-init) ====================
__global__ void zero_vmax_kernel() {
    int i = blockIdx.x * 256 + threadIdx.x;
    if (i < 2 * INNER) g_vmax[i] = 0u;
}

// ================= Kernel 1: q projection via warp-MMA (bf16 3-term) ===========
#define OP_AHI 0
#define OP_ALO 9216
#define OP_BHI 18432
#define OP_BLO 27648

__global__ __launch_bounds__(128) void qproj_mma_kernel(
    const float* __restrict__ x, const float* __restrict__ px,
    const float* __restrict__ Wq)
{
    __shared__ __align__(16) char sm[36864];
    const int i0 = blockIdx.x * 64;
    const int g  = blockIdx.y;
    const int c0 = g * 64;
    const float* src = (g < 4) ? px : x;
    const int   base = (g & 3) * 128;
    const int tid = threadIdx.x;
    const int lane = tid & 31, wid = tid >> 5;
    const u32 smb = smem_u32(sm);

    float acc[8][4];
    #pragma unroll
    for (int nb = 0; nb < 8; nb++)
        #pragma unroll
        for (int u = 0; u < 4; u++) acc[nb][u] = 0.f;

    const u32 apos = (wid * 16 + (lane & 7) + ((lane >> 3) & 1) * 8) * SMSTRIDE
                   + ((lane >> 4) & 1) * 16;
    const u32 bpos = (lane & 7) * SMSTRIDE + ((lane >> 3) & 1) * 16;

    for (int k0 = 0; k0 < 128; k0 += 64) {
        __syncthreads();
        for (int idx = tid; idx < 2048; idx += 128) {
            int r = idx >> 5, c2 = idx & 31;
            float2 a = *(const float2*)&src[(size_t)(i0 + r) * DIMC + base + k0 + 2 * c2];
            float ah = bfhi(a.x), bh = bfhi(a.y);
            u32 so = r * SMSTRIDE + c2 * 4;
            *(u32*)(sm + OP_AHI + so) = pack_bf16(ah, bh);
            *(u32*)(sm + OP_ALO + so) = pack_bf16(a.x - ah, a.y - bh);
            float2 w = *(const float2*)&Wq[(c0 + r) * 128 + k0 + 2 * c2];
            float wh = bfhi(w.x), xh = bfhi(w.y);
            *(u32*)(sm + OP_BHI + so) = pack_bf16(wh, xh);
            *(u32*)(sm + OP_BLO + so) = pack_bf16(w.x - wh, w.y - xh);
        }
        __syncthreads();
        #pragma unroll
        for (int kb = 0; kb < 4; kb++) {
            u32 ah0, ah1, ah2, ah3, al0, al1, al2, al3;
            ldsm_x4(smb + OP_AHI + apos + kb * 32, ah0, ah1, ah2, ah3);
            ldsm_x4(smb + OP_ALO + apos + kb * 32, al0, al1, al2, al3);
            #pragma unroll
            for (int nb = 0; nb < 8; nb++) {
                u32 b0, b1, c0r, c1r;
                ldsm_x2(smb + OP_BHI + bpos + nb * (8 * SMSTRIDE) + kb * 32, b0, b1);
                mma16816(acc[nb], ah0, ah1, ah2, ah3, b0, b1);
                mma16816(acc[nb], al0, al1, al2, al3, b0, b1);
                ldsm_x2(smb + OP_BLO + bpos + nb * (8 * SMSTRIDE) + kb * 32, c0r, c1r);
                mma16816(acc[nb], ah0, ah1, ah2, ah3, c0r, c1r);
            }
        }
    }
    const int rA = wid * 16 + (lane >> 2), rB = rA + 8;
    #pragma unroll
    for (int nb = 0; nb < 8; nb++) {
        int col = nb * 8 + (lane & 3) * 2;
        *(float2*)&g_qT[(size_t)(i0 + rA) * DIMC + c0 + col] =
            make_float2(acc[nb][0], acc[nb][1]);
        *(float2*)&g_qT[(size_t)(i0 + rB) * DIMC + c0 + col] =
            make_float2(acc[nb][2], acc[nb][3]);
    }
}

// ================= Kernel 2: offset network ====================================
__global__ __launch_bounds__(128) void offset_kernel(
    const float* __restrict__ Wdw, const float* __restrict__ bdw,
    const float* __restrict__ Wp)
{
    const int g = blockIdx.y;
    const int t = blockIdx.x * 128 + threadIdx.x;
    const int pbase = 4 * t - 1;
    float s = 0.f;
    for (int c = 0; c < 64; c++) {
        float hv = bdw[c];
        #pragma unroll
        for (int k = 0; k < 6; k++) {
            int p = pbase + k;
            if (p >= 0 && p < N_SEQ) hv += Wdw[c * 6 + k] * g_qT[(size_t)p * DIMC + g * 64 + c];
        }
        hv = 0.5f * hv * (1.f + erff(hv * 0.7071067811865476f));
        s += Wp[c] * hv;
    }
    float off = tanhf(s) * 4.0f;
    float vg  = 2.0f * ((float)t + off) / 1023.0f - 1.0f;
    float pos = ((vg + 1.0f) * (float)N_SEQ - 1.0f) * 0.5f;
    g_pos[g * M_SEQ + t] = pos;
}

// ================= Kernel 3: fused gridsample + k/v projection =================
// bf16 3-term GEMM; epilogue: K -> int8 2-term + row scale, V -> fp32 + absmax
#define KV_AHI 0
#define KV_ALO 9216
#define KV_BHI 18432
#define KV_BLO 27648

__global__ __launch_bounds__(128) void kvproj_mma_kernel(
    const float* __restrict__ x, const float* __restrict__ px,
    const float* __restrict__ Wk, const float* __restrict__ Wv)
{
    __shared__ __align__(16) char sm[36864];
    const int t0 = blockIdx.x * 64;
    const int g  = blockIdx.y;
    const int s  = blockIdx.z & 1;
    const int which = blockIdx.z >> 1;
    const int c0 = g * 64;
    const float* W = which ? Wv : Wk;
    const float* src = (s == 0) ? px : x;
    const int tid = threadIdx.x;
    const int lane = tid & 31, wid = tid >> 5;
    const u32 smb = smem_u32(sm);

    for (int idx = tid; idx < 2048; idx += 128) {
        int r = idx >> 5, c2 = idx & 31;
        const float pos = g_pos[g * M_SEQ + t0 + r];
        const float x0f = floorf(pos);
        const float w1 = pos - x0f;
        const int p0 = (int)x0f;
        const int ch = c0 + 2 * c2;
        float ax = 0.f, ay = 0.f;
        if (p0 >= 0 && p0 < N_SEQ) {
            float2 f = *(const float2*)&src[(size_t)p0 * DIMC + ch];
            ax += (1.f - w1) * f.x; ay += (1.f - w1) * f.y;
        }
        if (p0 + 1 >= 0 && p0 + 1 < N_SEQ) {
            float2 f = *(const float2*)&src[(size_t)(p0 + 1) * DIMC + ch];
            ax += w1 * f.x; ay += w1 * f.y;
        }
        float ah = bfhi(ax), bh = bfhi(ay);
        u32 so = r * SMSTRIDE + c2 * 4;
        *(u32*)(sm + KV_AHI + so) = pack_bf16(ah, bh);
        *(u32*)(sm + KV_ALO + so) = pack_bf16(ax - ah, ay - bh);
        float2 w = *(const float2*)&W[(c0 + r) * 64 + 2 * c2];
        float wh = bfhi(w.x), xh = bfhi(w.y);
        *(u32*)(sm + KV_BHI + so) = pack_bf16(wh, xh);
        *(u32*)(sm + KV_BLO + so) = pack_bf16(w.x - wh, w.y - xh);
    }
    __syncthreads();

    float acc[8][4];
    #pragma unroll
    for (int nb = 0; nb < 8; nb++)
        #pragma unroll
        for (int u = 0; u < 4; u++) acc[nb][u] = 0.f;

    const u32 apos = (wid * 16 + (lane & 7) + ((lane >> 3) & 1) * 8) * SMSTRIDE
                   + ((lane >> 4) & 1) * 16;
    const u32 bpos = (lane & 7) * SMSTRIDE + ((lane >> 3) & 1) * 16;

    #pragma unroll
    for (int kb = 0; kb < 4; kb++) {
        u32 ah0, ah1, ah2, ah3, al0, al1, al2, al3;
        ldsm_x4(smb + KV_AHI + apos + kb * 32, ah0, ah1, ah2, ah3);
        ldsm_x4(smb + KV_ALO + apos + kb * 32, al0, al1, al2, al3);
        #pragma unroll
        for (int nb = 0; nb < 8; nb++) {
            u32 b0, b1, c0r, c1r;
            ldsm_x2(smb + KV_BHI + bpos + nb * (8 * SMSTRIDE) + kb * 32, b0, b1);
            mma16816(acc[nb], ah0, ah1, ah2, ah3, b0, b1);
            mma16816(acc[nb], al0, al1, al2, al3, b0, b1);
            ldsm_x2(smb + KV_BLO + bpos + nb * (8 * SMSTRIDE) + kb * 32, c0r, c1r);
            mma16816(acc[nb], ah0, ah1, ah2, ah3, c0r, c1r);
        }
    }

    const int rA = wid * 16 + (lane >> 2), rB = rA + 8;
    const int tA = s * M_SEQ + t0 + rA;
    const int tB = s * M_SEQ + t0 + rB;

    if (which == 0) {
        // ---- K: per-row 2-term int8 quantization ----
        float mA = 0.f, mB = 0.f;
        #pragma unroll
        for (int nb = 0; nb < 8; nb++) {
            mA = fmaxf(mA, fmaxf(fabsf(acc[nb][0]), fabsf(acc[nb][1])));
            mB = fmaxf(mB, fmaxf(fabsf(acc[nb][2]), fabsf(acc[nb][3])));
        }
        mA = fmaxf(mA, __shfl_xor_sync(0xffffffffu, mA, 1));
        mA = fmaxf(mA, __shfl_xor_sync(0xffffffffu, mA, 2));
        mB = fmaxf(mB, __shfl_xor_sync(0xffffffffu, mB, 1));
        mB = fmaxf(mB, __shfl_xor_sync(0xffffffffu, mB, 2));
        mA = fmaxf(mA, 1e-30f); mB = fmaxf(mB, 1e-30f);
        float iA = 16256.f / mA, iB = 16256.f / mB;
        #pragma unroll
        for (int nb = 0; nb < 8; nb++) {
            int col = nb * 8 + (lane & 3) * 2;
            float a0v = acc[nb][0] * iA, a1v = acc[nb][1] * iA;
            float h0 = rintf(a0v * 0.0078125f), h1 = rintf(a1v * 0.0078125f);
            *(u16*)&g_kq[(size_t)tA * 1024 + g * 128 + col]      = pk2s8(h0, h1);
            *(u16*)&g_kq[(size_t)tA * 1024 + g * 128 + 64 + col] =
                pk2s8(a0v - 128.f * h0, a1v - 128.f * h1);
            float b0v = acc[nb][2] * iB, b1v = acc[nb][3] * iB;
            float g0 = rintf(b0v * 0.0078125f), g1 = rintf(b1v * 0.0078125f);
            *(u16*)&g_kq[(size_t)tB * 1024 + g * 128 + col]      = pk2s8(g0, g1);
            *(u16*)&g_kq[(size_t)tB * 1024 + g * 128 + 64 + col] =
                pk2s8(b0v - 128.f * g0, b1v - 128.f * g1);
        }
        if ((lane & 3) == 0) {
            g_ksc[(size_t)(s * HEADS + g) * M_SEQ + t0 + rA] = mA / 16256.f;
            g_ksc[(size_t)(s * HEADS + g) * M_SEQ + t0 + rB] = mB / 16256.f;
        }
    } else {
        // ---- V: fp32 out + per-channel absmax ----
        float cmax[8][2];
        #pragma unroll
        for (int nb = 0; nb < 8; nb++) {
            int col = nb * 8 + (lane & 3) * 2;
            *(float2*)&g_vf[(size_t)tA * INNER + c0 + col] =
                make_float2(acc[nb][0], acc[nb][1]);
            *(float2*)&g_vf[(size_t)tB * INNER + c0 + col] =
                make_float2(acc[nb][2], acc[nb][3]);
            cmax[nb][0] = fmaxf(fabsf(acc[nb][0]), fabsf(acc[nb][2]));
            cmax[nb][1] = fmaxf(fabsf(acc[nb][1]), fabsf(acc[nb][3]));
        }
        #pragma unroll
        for (int nb = 0; nb < 8; nb++) {
            #pragma unroll
            for (int u = 0; u < 2; u++) {
                float m = cmax[nb][u];
                m = fmaxf(m, __shfl_xor_sync(0xffffffffu, m, 4));
                m = fmaxf(m, __shfl_xor_sync(0xffffffffu, m, 8));
                m = fmaxf(m, __shfl_xor_sync(0xffffffffu, m, 16));
                if ((lane >> 2) == 0) {
                    int col = nb * 8 + (lane & 3) * 2 + u;
                    atomicMax(&g_vmax[s * INNER + c0 + col], __float_as_uint(m));
                }
            }
        }
    }
}

// ================= Kernel 3b: V int8 prep ======================================
__global__ __launch_bounds__(256) void vprep_kernel()
{
    __shared__ float ts[32][33];
    const int chc = blockIdx.x;        // 16 chunks of 32 ch
    const int jc  = blockIdx.y;        // 32 chunks of 32 j
    const int s   = blockIdx.z;
    const int tid = threadIdx.x;
    const int ch0 = chc * 32, j0 = jc * 32;
    {
        int r = tid >> 3, c4 = (tid & 7) * 4;
        float4 v = *(const float4*)&g_vf[((size_t)(s * M_SEQ + j0 + r)) * INNER + ch0 + c4];
        ts[r][c4] = v.x; ts[r][c4 + 1] = v.y; ts[r][c4 + 2] = v.z; ts[r][c4 + 3] = v.w;
    }
    __syncthreads();
    {
        int chl = tid >> 3, j4 = (tid & 7) * 4;
        float vmax = fmaxf(__uint_as_float(g_vmax[s * INNER + ch0 + chl]), 1e-30f);
        float inv = 16256.f / vmax;
        u32 w1 = 0, w0 = 0;
        #pragma unroll
        for (int i = 0; i < 4; i++) {
            float av = ts[j4 + i][chl] * inv;
            float h = rintf(av * 0.0078125f);
            int i1 = (int)h, i0v = (int)rintf(av - 128.f * h);
            w1 |= (u32)(i1 & 0xff) << (8 * i);
            w0 |= (u32)(i0v & 0xff) << (8 * i);
        }
        size_t base = ((size_t)(s * INNER + ch0 + chl) * 32 + jc) * 64;
        *(u32*)&g_vq[base + j4]      = w1;
        *(u32*)&g_vq[base + 32 + j4] = w0;
        if (jc == 0 && (tid & 7) == 0)
            g_vsc[s * INNER + ch0 + chl] = vmax / 16256.f;
    }
}

// ================= Kernel 4: int8 flash attention ==============================
// CTA: 128 q-rows, 8 warps, 256 thr. Bc=32 keys, double-buffered cp.async.
// smem layout (bytes):
#define KOFF 0          // K tile: 32 rows x 144 (128B data, conflict-free stride)
#define VOFF 4608       // V tile: 64 ch x 80 (64B data)
#define SKOFF 9728      // 32 floats
#define BUFSZ 9856
#define POFF 19712      // P strip: 128 rows x 80 (64B data)
#define SQOFF 29952     // 128 floats (sq*128)
#define QSOFF 0         // Q strip 128 x 144 (pre-loop; aliases buffers)

__global__ __launch_bounds__(256) void attn_kernel()
{
    __shared__ __align__(16) char sm[30464];
    const int i0 = blockIdx.x * 128;
    const int h  = blockIdx.y;
    const int s  = blockIdx.z;
    const int tid = threadIdx.x;
    const int lane = tid & 31;
    const int wid = tid >> 5;
    const u32 smb = smem_u32(sm);

    // ---- Q: per-row 2-term int8 quantization into strip ----
    {
        const float* qbase = g_qT + (size_t)i0 * DIMC + h * 64;
        #pragma unroll 4
        for (int it = 0; it < 16; it++) {
            int r = wid + it * 8;
            float2 qv = *(const float2*)&qbase[(size_t)r * DIMC + 2 * lane];
            float a = qv.x * QSCL, b = qv.y * QSCL;
            float m = fmaxf(fabsf(a), fabsf(b));
            #pragma unroll
            for (int o = 16; o >= 1; o >>= 1)
                m = fmaxf(m, __shfl_xor_sync(0xffffffffu, m, o));
            m = fmaxf(m, 1e-30f);
            float inv = 16256.f / m;
            float av = a * inv, bv = b * inv;
            float h1 = rintf(av * 0.0078125f), h2 = rintf(bv * 0.0078125f);
            *(u16*)(sm + QSOFF + r * SMSTRIDE + 2 * lane)      = pk2s8(h1, h2);
            *(u16*)(sm + QSOFF + r * SMSTRIDE + 64 + 2 * lane) =
                pk2s8(av - 128.f * h1, bv - 128.f * h2);
            if (lane == 0) *(float*)(sm + SQOFF + r * 4) = (m / 16256.f) * 128.f;
        }
    }
    __syncthreads();

    const int arow = wid * 16 + (lane >> 2);
    const int rA = arow, rB = arow + 8;

    // ---- Q A-fragments (manual loads, PTX m16n8k32 layout) ----
    u32 qa1[2][4], qa0[2][4];
    #pragma unroll
    for (int c = 0; c < 2; c++) {
        const char* bse = sm + QSOFF + arow * SMSTRIDE + c * 32 + 4 * (lane & 3);
        qa1[c][0] = *(const u32*)bse;
        qa1[c][1] = *(const u32*)(bse + 8 * SMSTRIDE);
        qa1[c][2] = *(const u32*)(bse + 16);
        qa1[c][3] = *(const u32*)(bse + 8 * SMSTRIDE + 16);
        qa0[c][0] = *(const u32*)(bse + 64);
        qa0[c][1] = *(const u32*)(bse + 8 * SMSTRIDE + 64);
        qa0[c][2] = *(const u32*)(bse + 80);
        qa0[c][3] = *(const u32*)(bse + 8 * SMSTRIDE + 80);
    }
    const float sqA = *(const float*)(sm + SQOFF + rA * 4);
    const float sqB = *(const float*)(sm + SQOFF + rB * 4);

    // ---- V channel scale preload ----
    float svc[8][2];
    {
        const float* vscb = g_vsc + s * INNER + h * 64;
        #pragma unroll
        for (int nd = 0; nd < 8; nd++) {
            svc[nd][0] = vscb[nd * 8 + 2 * (lane & 3)]     * 0.0078740157480315f;
            svc[nd][1] = vscb[nd * 8 + 2 * (lane & 3) + 1] * 0.0078740157480315f;
        }
    }
    __syncthreads();   // Q frags + scales read; strip region free for buffers

    const u8* kqb = g_kq + (size_t)s * M_SEQ * 1024 + h * 128;
    const u8* vqb = g_vq + (size_t)(s * INNER + h * 64) * 2048;
    const float* kscb = g_ksc + (size_t)(s * HEADS + h) * M_SEQ;

    const int r5 = tid >> 3, seg8 = tid & 7;
    const int vch = tid >> 2, seg4 = tid & 3;

    float oacc[8][4];
    #pragma unroll
    for (int nd = 0; nd < 8; nd++)
        #pragma unroll
        for (int u = 0; u < 4; u++) oacc[nd][u] = 0.f;
    float mA = -1e30f, mB = -1e30f, lA = 0.f, lB = 0.f;

    // prologue: tile 0 -> buffer 0
    {
        cp_async16(smb + KOFF + r5 * SMSTRIDE + seg8 * 16,
                   kqb + (size_t)r5 * 1024 + seg8 * 16);
        cp_async16(smb + VOFF + vch * 80 + seg4 * 16,
                   vqb + (size_t)vch * 2048 + seg4 * 16);
        if (tid < 8)
            cp_async16(smb + SKOFF + tid * 16, kscb + tid * 4);
        CP_COMMIT();
    }

    for (int t = 0; t < 32; t++) {
        if (t + 1 < 32) {
            int jr = (t + 1) * 32;
            u32 so = smb + ((t + 1) & 1) * BUFSZ;
            cp_async16(so + KOFF + r5 * SMSTRIDE + seg8 * 16,
                       kqb + (size_t)(jr + r5) * 1024 + seg8 * 16);
            cp_async16(so + VOFF + vch * 80 + seg4 * 16,
                       vqb + (size_t)vch * 2048 + (size_t)(t + 1) * 64 + seg4 * 16);
            if (tid < 8)
                cp_async16(so + SKOFF + tid * 16, kscb + jr + tid * 4);
            CP_COMMIT();
            CP_WAIT(1);
        } else {
            CP_WAIT(0);
        }
        __syncthreads();
        const char* kb = sm + (t & 1) * BUFSZ + KOFF;
        const char* vb = sm + (t & 1) * BUFSZ + VOFF;
        const float* skb = (const float*)(sm + (t & 1) * BUFSZ + SKOFF);

        // ---- S = int8 2-term (hh + cross; ll dropped) ----
        float sf[4][4];
        #pragma unroll
        for (int nb = 0; nb < 4; nb++) {
            const char* krow = kb + (nb * 8 + (lane >> 2)) * SMSTRIDE + 4 * (lane & 3);
            u32 k1c0a = *(const u32*)krow,        k1c0b = *(const u32*)(krow + 16);
            u32 k1c1a = *(const u32*)(krow + 32), k1c1b = *(const u32*)(krow + 48);
            u32 k0c0a = *(const u32*)(krow + 64), k0c0b = *(const u32*)(krow + 80);
            u32 k0c1a = *(const u32*)(krow + 96), k0c1b = *(const u32*)(krow + 112);
            int hh[4] = {0, 0, 0, 0}, cr[4] = {0, 0, 0, 0};
            mma_s8(hh, qa1[0], k1c0a, k1c0b);
            mma_s8(hh, qa1[1], k1c1a, k1c1b);
            mma_s8(cr, qa1[0], k0c0a, k0c0b);
            mma_s8(cr, qa1[1], k0c1a, k0c1b);
            mma_s8(cr, qa0[0], k1c0a, k1c0b);
            mma_s8(cr, qa0[1], k1c1a, k1c1b);
            float2 sk01 = *(const float2*)&skb[nb * 8 + 2 * (lane & 3)];
            sf[nb][0] = ((float)hh[0] * 128.f + (float)cr[0]) * (sqA * sk01.x);
            sf[nb][1] = ((float)hh[1] * 128.f + (float)cr[1]) * (sqA * sk01.y);
            sf[nb][2] = ((float)hh[2] * 128.f + (float)cr[2]) * (sqB * sk01.x);
            sf[nb][3] = ((float)hh[3] * 128.f + (float)cr[3]) * (sqB * sk01.y);
        }

        // ---- online softmax (base-2) ----
        float tA = -1e30f, tB = -1e30f;
        #pragma unroll
        for (int nb = 0; nb < 4; nb++) {
            tA = fmaxf(tA, fmaxf(sf[nb][0], sf[nb][1]));
            tB = fmaxf(tB, fmaxf(sf[nb][2], sf[nb][3]));
        }
        tA = fmaxf(tA, __shfl_xor_sync(0xffffffffu, tA, 1));
        tA = fmaxf(tA, __shfl_xor_sync(0xffffffffu, tA, 2));
        tB = fmaxf(tB, __shfl_xor_sync(0xffffffffu, tB, 1));
        tB = fmaxf(tB, __shfl_xor_sync(0xffffffffu, tB, 2));
        float mAn = fmaxf(mA, tA), mBn = fmaxf(mB, tB);
        float cA = ex2f(mA - mAn), cB = ex2f(mB - mBn);
        mA = mAn; mB = mBn;
        float sA = 0.f, sB = 0.f;
        #pragma unroll
        for (int nb = 0; nb < 4; nb++) {
            sf[nb][0] = ex2f(sf[nb][0] - mAn);
            sf[nb][1] = ex2f(sf[nb][1] - mAn);
            sf[nb][2] = ex2f(sf[nb][2] - mBn);
            sf[nb][3] = ex2f(sf[nb][3] - mBn);
            sA += sf[nb][0] + sf[nb][1];
            sB += sf[nb][2] + sf[nb][3];
        }
        sA += __shfl_xor_sync(0xffffffffu, sA, 1);
        sA += __shfl_xor_sync(0xffffffffu, sA, 2);
        sB += __shfl_xor_sync(0xffffffffu, sB, 1);
        sB += __shfl_xor_sync(0xffffffffu, sB, 2);
        lA = lA * cA + sA;
        lB = lB * cB + sB;
        #pragma unroll
        for (int nd = 0; nd < 8; nd++) {
            oacc[nd][0] *= cA; oacc[nd][1] *= cA;
            oacc[nd][2] *= cB; oacc[nd][3] *= cB;
        }

        // ---- P: 2-term int8 strip (p = (128*p1 + p0)/16256, p in [0,1]) ----
        #pragma unroll
        for (int nb = 0; nb < 4; nb++) {
            int col = nb * 8 + 2 * (lane & 3);
            float p1a = rintf(sf[nb][0] * 127.f), p1b = rintf(sf[nb][1] * 127.f);
            *(u16*)(sm + POFF + rA * 80 + col) = pk2s8(p1a, p1b);
            *(u16*)(sm + POFF + rA * 80 + 32 + col) =
                pk2s8(sf[nb][0] * 16256.f - 128.f * p1a, sf[nb][1] * 16256.f - 128.f * p1b);
            float p1c = rintf(sf[nb][2] * 127.f), p1d = rintf(sf[nb][3] * 127.f);
            *(u16*)(sm + POFF + rB * 80 + col) = pk2s8(p1c, p1d);
            *(u16*)(sm + POFF + rB * 80 + 32 + col) =
                pk2s8(sf[nb][2] * 16256.f - 128.f * p1c, sf[nb][3] * 16256.f - 128.f * p1d);
        }
        __syncwarp();
        u32 pa1[4], pa0[4];
        {
            const char* bse = sm + POFF + arow * 80 + 4 * (lane & 3);
            pa1[0] = *(const u32*)bse;
            pa1[1] = *(const u32*)(bse + 8 * 80);
            pa1[2] = *(const u32*)(bse + 16);
            pa1[3] = *(const u32*)(bse + 8 * 80 + 16);
            pa0[0] = *(const u32*)(bse + 32);
            pa0[1] = *(const u32*)(bse + 8 * 80 + 32);
            pa0[2] = *(const u32*)(bse + 48);
            pa0[3] = *(const u32*)(bse + 8 * 80 + 48);
        }

        // ---- O += P V (int8 hh + cross) ----
        #pragma unroll
        for (int nd = 0; nd < 8; nd++) {
            const char* vrow = vb + (nd * 8 + (lane >> 2)) * 80 + 4 * (lane & 3);
            u32 v1a = *(const u32*)vrow,        v1b = *(const u32*)(vrow + 16);
            u32 v0a = *(const u32*)(vrow + 32), v0b = *(const u32*)(vrow + 48);
            int Oh[4] = {0, 0, 0, 0}, Oc[4] = {0, 0, 0, 0};
            mma_s8(Oh, pa1, v1a, v1b);
            mma_s8(Oc, pa1, v0a, v0b);
            mma_s8(Oc, pa0, v1a, v1b);
            #pragma unroll
            for (int u = 0; u < 4; u++)
                oacc[nd][u] += (float)Oh[u] * 128.f + (float)Oc[u];
        }
        __syncthreads();
    }

    // ---- epilogue: apply sv & 1/l, store g_att[s][i][c] ----
    float invA = 1.f / lA, invB = 1.f / lB;
    float* oA = g_att + (size_t)s * N_SEQ * INNER + (size_t)(i0 + rA) * INNER + h * 64;
    float* oB = g_att + (size_t)s * N_SEQ * INNER + (size_t)(i0 + rB) * INNER + h * 64;
    #pragma unroll
    for (int nd = 0; nd < 8; nd++) {
        int col = nd * 8 + (lane & 3) * 2;
        *(float2*)&oA[col] = make_float2(oacc[nd][0] * svc[nd][0] * invA,
                                         oacc[nd][1] * svc[nd][1] * invA);
        *(float2*)&oB[col] = make_float2(oacc[nd][2] * svc[nd][0] * invB,
                                         oacc[nd][3] * svc[nd][1] * invB);
    }
}

// ================= Kernel 5: stream-mean + Wo GEMM (warp-MMA bf16-3) ===========
__global__ __launch_bounds__(128) void outproj_mma_kernel(
    const float* __restrict__ Wo, const float* __restrict__ bo,
    float* __restrict__ out)
{
    __shared__ __align__(16) char sm[36864];
    const int i0 = blockIdx.x * 64;
    const int d0 = blockIdx.y * 64;
    const int tid = threadIdx.x;
    const int lane = tid & 31, wid = tid >> 5;
    const u32 smb = smem_u32(sm);

    float acc[8][4];
    #pragma unroll
    for (int nb = 0; nb < 8; nb++)
        #pragma unroll
        for (int u = 0; u < 4; u++) acc[nb][u] = 0.f;

    const u32 apos = (wid * 16 + (lane & 7) + ((lane >> 3) & 1) * 8) * SMSTRIDE
                   + ((lane >> 4) & 1) * 16;
    const u32 bpos = (lane & 7) * SMSTRIDE + ((lane >> 3) & 1) * 16;

    for (int k0 = 0; k0 < 512; k0 += 64) {
        __syncthreads();
        for (int idx = tid; idx < 2048; idx += 128) {
            int r = idx >> 5, c2 = idx & 31;
            const float* a0p = &g_att[(size_t)(i0 + r) * INNER + k0 + 2 * c2];
            float2 u0 = *(const float2*)a0p;
            float2 u1 = *(const float2*)(a0p + (size_t)N_SEQ * INNER);
            float ax = 0.5f * (u0.x + u1.x), ay = 0.5f * (u0.y + u1.y);
            float ah = bfhi(ax), bh = bfhi(ay);
            u32 so = r * SMSTRIDE + c2 * 4;
            *(u32*)(sm + OP_AHI + so) = pack_bf16(ah, bh);
            *(u32*)(sm + OP_ALO + so) = pack_bf16(ax - ah, ay - bh);
            float2 w = *(const float2*)&Wo[(d0 + r) * INNER + k0 + 2 * c2];
            float wh = bfhi(w.x), xh = bfhi(w.y);
            *(u32*)(sm + OP_BHI + so) = pack_bf16(wh, xh);
            *(u32*)(sm + OP_BLO + so) = pack_bf16(w.x - wh, w.y - xh);
        }
        __syncthreads();

        #pragma unroll
        for (int kb = 0; kb < 4; kb++) {
            u32 ah0, ah1, ah2, ah3, al0, al1, al2, al3;
            ldsm_x4(smb + OP_AHI + apos + kb * 32, ah0, ah1, ah2, ah3);
            ldsm_x4(smb + OP_ALO + apos + kb * 32, al0, al1, al2, al3);
            #pragma unroll
            for (int nb = 0; nb < 8; nb++) {
                u32 b0, b1, c0r, c1r;
                ldsm_x2(smb + OP_BHI + bpos + nb * (8 * SMSTRIDE) + kb * 32, b0, b1);
                mma16816(acc[nb], ah0, ah1, ah2, ah3, b0, b1);
                mma16816(acc[nb], al0, al1, al2, al3, b0, b1);
                ldsm_x2(smb + OP_BLO + bpos + nb * (8 * SMSTRIDE) + kb * 32, c0r, c1r);
                mma16816(acc[nb], ah0, ah1, ah2, ah3, c0r, c1r);
            }
        }
    }

    const int rA = wid * 16 + (lane >> 2), rB = rA + 8;
    #pragma unroll
    for (int nb = 0; nb < 8; nb++) {
        int col = nb * 8 + (lane & 3) * 2;
        float b0 = bo[d0 + col], b1 = bo[d0 + col + 1];
        *(float2*)&out[(size_t)(i0 + rA) * DIMC + d0 + col] =
            make_float2(acc[nb][0] + b0, acc[nb][1] + b1);
        *(float2*)&out[(size_t)(i0 + rB) * DIMC + d0 + col] =
            make_float2(acc[nb][2] + b0, acc[nb][3] + b1);
    }
}

// ================= launch ======================================================
extern "C" void kernel_launch(void* const* d_in, const int* in_sizes, int n_in,
                              void* d_out, int out_size)
{
    const float* x   = (const float*)d_in[0];
    const float* px  = (const float*)d_in[1];
    const float* Wq  = (const float*)d_in[2];
    const float* Wk  = (const float*)d_in[3];
    const float* Wv  = (const float*)d_in[4];
    const float* Wo  = (const float*)d_in[5];
    const float* bo  = (const float*)d_in[6];
    const float* Wdw = (const float*)d_in[7];
    const float* bdw = (const float*)d_in[8];
    const float* Wp  = (const float*)d_in[9];
    float* out = (float*)d_out;

    zero_vmax_kernel<<<4, 256>>>();
    qproj_mma_kernel<<<dim3(64, 8), 128>>>(x, px, Wq);
    offset_kernel<<<dim3(8, 8), 128>>>(Wdw, bdw, Wp);
    kvproj_mma_kernel<<<dim3(16, 8, 4), 128>>>(x, px, Wk, Wv);
    vprep_kernel<<<dim3(16, 32, 2), 256>>>();
    attn_kernel<<<dim3(32, HEADS, 2), 256>>>();
    outproj_mma_kernel<<<dim3(64, 8), 128>>>(Wo, bo, out);
}

// round 11
// speedup vs baseline: 1.7722x; 1.7722x over previous
#include <cuda_runtime.h>
#include <cuda_bf16.h>
#include <math.h>

typedef unsigned int u32;
typedef unsigned short u16;
typedef unsigned char u8;
typedef unsigned long long u64;
typedef unsigned long long ull;

#define N_SEQ 4096
#define M_SEQ 1024
#define DIMC  512
#define INNER 512
#define HEADS 8
#define GROUPS 8

// ---------------- warp-MMA helpers -------------------------------------------
__device__ __forceinline__ u32 smem_u32(const void* p) {
    u32 a;
    asm("{ .reg .u64 t; cvta.to.shared.u64 t, %1; cvt.u32.u64 %0, t; }" : "=r"(a) : "l"(p));
    return a;
}
__device__ __forceinline__ float ex2f(float x) {
    float r; asm("ex2.approx.ftz.f32 %0, %1;" : "=f"(r) : "f"(x)); return r;
}
__device__ __forceinline__ void ldsm_x4(u32 addr, u32& r0, u32& r1, u32& r2, u32& r3) {
    asm volatile("ldmatrix.sync.aligned.m8n8.x4.shared.b16 {%0,%1,%2,%3}, [%4];"
        : "=r"(r0), "=r"(r1), "=r"(r2), "=r"(r3) : "r"(addr));
}
__device__ __forceinline__ void ldsm_x2(u32 addr, u32& r0, u32& r1) {
    asm volatile("ldmatrix.sync.aligned.m8n8.x2.shared.b16 {%0,%1}, [%2];"
        : "=r"(r0), "=r"(r1) : "r"(addr));
}
__device__ __forceinline__ void ldsm_x2_t(u32 addr, u32& r0, u32& r1) {
    asm volatile("ldmatrix.sync.aligned.m8n8.x2.trans.shared.b16 {%0,%1}, [%2];"
        : "=r"(r0), "=r"(r1) : "r"(addr));
}
__device__ __forceinline__ void mma16816(float* c, u32 a0, u32 a1, u32 a2, u32 a3,
                                         u32 b0, u32 b1) {
    asm volatile(
        "mma.sync.aligned.m16n8k16.row.col.f32.bf16.bf16.f32 "
        "{%0,%1,%2,%3}, {%4,%5,%6,%7}, {%8,%9}, {%0,%1,%2,%3};"
        : "+f"(c[0]), "+f"(c[1]), "+f"(c[2]), "+f"(c[3])
        : "r"(a0), "r"(a1), "r"(a2), "r"(a3), "r"(b0), "r"(b1));
}
__device__ __forceinline__ u32 pack_bf16(float a, float b) {
    return ((u32)__bfloat16_as_ushort(__float2bfloat16(b)) << 16) |
           (u32)__bfloat16_as_ushort(__float2bfloat16(a));
}
__device__ __forceinline__ float bfhi(float x) {
    return __bfloat162float(__float2bfloat16(x));
}
__device__ __forceinline__ void cp_async16(u32 s, const void* g) {
    asm volatile("cp.async.cg.shared.global [%0], [%1], 16;" :: "r"(s), "l"(g));
}
#define CP_COMMIT() asm volatile("cp.async.commit_group;" ::: "memory")
#define CP_WAIT(n)  asm volatile("cp.async.wait_group %0;" :: "n"(n) : "memory")

// ---------------- scratch (static device globals) ------------------------------
__device__ float g_qT[N_SEQ * DIMC];                 // q[i][c]
__device__ float g_pos[GROUPS * M_SEQ];
__device__ __nv_bfloat16 g_khi[2 * M_SEQ * INNER];   // k hi  [s][t][c]
__device__ __nv_bfloat16 g_klo[2 * M_SEQ * INNER];   // k lo
__device__ __nv_bfloat16 g_vhi[2 * M_SEQ * INNER];   // v hi  [s][t][c]
__device__ __nv_bfloat16 g_vlo[2 * M_SEQ * INNER];   // v lo
__device__ float g_att[2 * N_SEQ * INNER];           // attn out [s][i][c]

#define SMSTRIDE 144
#define QSCL 0.1803368801111204f   // 0.125 * log2(e)

// ================= Kernel 1: q projection via warp-MMA =========================
#define OP_AHI 0
#define OP_ALO 9216
#define OP_BHI 18432
#define OP_BLO 27648

__global__ __launch_bounds__(128) void qproj_mma_kernel(
    const float* __restrict__ x, const float* __restrict__ px,
    const float* __restrict__ Wq)
{
    __shared__ __align__(16) char sm[36864];
    const int i0 = blockIdx.x * 64;
    const int g  = blockIdx.y;
    const int c0 = g * 64;
    const float* src = (g < 4) ? px : x;
    const int   base = (g & 3) * 128;
    const int tid = threadIdx.x;
    const int lane = tid & 31, wid = tid >> 5;
    const u32 smb = smem_u32(sm);

    float acc[8][4];
    #pragma unroll
    for (int nb = 0; nb < 8; nb++)
        #pragma unroll
        for (int u = 0; u < 4; u++) acc[nb][u] = 0.f;

    const u32 apos = (wid * 16 + (lane & 7) + ((lane >> 3) & 1) * 8) * SMSTRIDE
                   + ((lane >> 4) & 1) * 16;
    const u32 bpos = (lane & 7) * SMSTRIDE + ((lane >> 3) & 1) * 16;

    for (int k0 = 0; k0 < 128; k0 += 64) {
        __syncthreads();
        for (int idx = tid; idx < 2048; idx += 128) {
            int r = idx >> 5, c2 = idx & 31;
            float2 a = *(const float2*)&src[(size_t)(i0 + r) * DIMC + base + k0 + 2 * c2];
            float ah = bfhi(a.x), bh = bfhi(a.y);
            u32 so = r * SMSTRIDE + c2 * 4;
            *(u32*)(sm + OP_AHI + so) = pack_bf16(ah, bh);
            *(u32*)(sm + OP_ALO + so) = pack_bf16(a.x - ah, a.y - bh);
            float2 w = *(const float2*)&Wq[(c0 + r) * 128 + k0 + 2 * c2];
            float wh = bfhi(w.x), xh = bfhi(w.y);
            *(u32*)(sm + OP_BHI + so) = pack_bf16(wh, xh);
            *(u32*)(sm + OP_BLO + so) = pack_bf16(w.x - wh, w.y - xh);
        }
        __syncthreads();
        #pragma unroll
        for (int kb = 0; kb < 4; kb++) {
            u32 ah0, ah1, ah2, ah3, al0, al1, al2, al3;
            ldsm_x4(smb + OP_AHI + apos + kb * 32, ah0, ah1, ah2, ah3);
            ldsm_x4(smb + OP_ALO + apos + kb * 32, al0, al1, al2, al3);
            #pragma unroll
            for (int nb = 0; nb < 8; nb++) {
                u32 b0, b1, c0r, c1r;
                ldsm_x2(smb + OP_BHI + bpos + nb * (8 * SMSTRIDE) + kb * 32, b0, b1);
                mma16816(acc[nb], ah0, ah1, ah2, ah3, b0, b1);
                mma16816(acc[nb], al0, al1, al2, al3, b0, b1);
                ldsm_x2(smb + OP_BLO + bpos + nb * (8 * SMSTRIDE) + kb * 32, c0r, c1r);
                mma16816(acc[nb], ah0, ah1, ah2, ah3, c0r, c1r);
            }
        }
    }
    const int rA = wid * 16 + (lane >> 2), rB = rA + 8;
    #pragma unroll
    for (int nb = 0; nb < 8; nb++) {
        int col = nb * 8 + (lane & 3) * 2;
        *(float2*)&g_qT[(size_t)(i0 + rA) * DIMC + c0 + col] =
            make_float2(acc[nb][0], acc[nb][1]);
        *(float2*)&g_qT[(size_t)(i0 + rB) * DIMC + c0 + col] =
            make_float2(acc[nb][2], acc[nb][3]);
    }
}

// ================= Kernel 2: offset network ====================================
__global__ __launch_bounds__(128) void offset_kernel(
    const float* __restrict__ Wdw, const float* __restrict__ bdw,
    const float* __restrict__ Wp)
{
    const int g = blockIdx.y;
    const int t = blockIdx.x * 128 + threadIdx.x;
    const int pbase = 4 * t - 1;
    float s = 0.f;
    for (int c = 0; c < 64; c++) {
        float hv = bdw[c];
        #pragma unroll
        for (int k = 0; k < 6; k++) {
            int p = pbase + k;
            if (p >= 0 && p < N_SEQ) hv += Wdw[c * 6 + k] * g_qT[(size_t)p * DIMC + g * 64 + c];
        }
        hv = 0.5f * hv * (1.f + erff(hv * 0.7071067811865476f));
        s += Wp[c] * hv;
    }
    float off = tanhf(s) * 4.0f;
    float vg  = 2.0f * ((float)t + off) / 1023.0f - 1.0f;
    float pos = ((vg + 1.0f) * (float)N_SEQ - 1.0f) * 0.5f;
    g_pos[g * M_SEQ + t] = pos;
}

// ================= Kernel 3: fused gridsample + k/v projection =================
#define KV_AHI 0
#define KV_ALO 9216
#define KV_BHI 18432
#define KV_BLO 27648

__global__ __launch_bounds__(128) void kvproj_mma_kernel(
    const float* __restrict__ x, const float* __restrict__ px,
    const float* __restrict__ Wk, const float* __restrict__ Wv)
{
    __shared__ __align__(16) char sm[36864];
    const int t0 = blockIdx.x * 64;
    const int g  = blockIdx.y;
    const int s  = blockIdx.z & 1;
    const int which = blockIdx.z >> 1;
    const int c0 = g * 64;
    const float* W = which ? Wv : Wk;
    const float* src = (s == 0) ? px : x;
    __nv_bfloat16* ohi = which ? g_vhi : g_khi;
    __nv_bfloat16* olo = which ? g_vlo : g_klo;
    const int tid = threadIdx.x;
    const int lane = tid & 31, wid = tid >> 5;
    const u32 smb = smem_u32(sm);

    for (int idx = tid; idx < 2048; idx += 128) {
        int r = idx >> 5, c2 = idx & 31;
        const float pos = g_pos[g * M_SEQ + t0 + r];
        const float x0f = floorf(pos);
        const float w1 = pos - x0f;
        const int p0 = (int)x0f;
        const int ch = c0 + 2 * c2;
        float ax = 0.f, ay = 0.f;
        if (p0 >= 0 && p0 < N_SEQ) {
            float2 f = *(const float2*)&src[(size_t)p0 * DIMC + ch];
            ax += (1.f - w1) * f.x; ay += (1.f - w1) * f.y;
        }
        if (p0 + 1 >= 0 && p0 + 1 < N_SEQ) {
            float2 f = *(const float2*)&src[(size_t)(p0 + 1) * DIMC + ch];
            ax += w1 * f.x; ay += w1 * f.y;
        }
        float ah = bfhi(ax), bh = bfhi(ay);
        u32 so = r * SMSTRIDE + c2 * 4;
        *(u32*)(sm + KV_AHI + so) = pack_bf16(ah, bh);
        *(u32*)(sm + KV_ALO + so) = pack_bf16(ax - ah, ay - bh);
        float2 w = *(const float2*)&W[(c0 + r) * 64 + 2 * c2];
        float wh = bfhi(w.x), xh = bfhi(w.y);
        *(u32*)(sm + KV_BHI + so) = pack_bf16(wh, xh);
        *(u32*)(sm + KV_BLO + so) = pack_bf16(w.x - wh, w.y - xh);
    }
    __syncthreads();

    float acc[8][4];
    #pragma unroll
    for (int nb = 0; nb < 8; nb++)
        #pragma unroll
        for (int u = 0; u < 4; u++) acc[nb][u] = 0.f;

    const u32 apos = (wid * 16 + (lane & 7) + ((lane >> 3) & 1) * 8) * SMSTRIDE
                   + ((lane >> 4) & 1) * 16;
    const u32 bpos = (lane & 7) * SMSTRIDE + ((lane >> 3) & 1) * 16;

    #pragma unroll
    for (int kb = 0; kb < 4; kb++) {
        u32 ah0, ah1, ah2, ah3, al0, al1, al2, al3;
        ldsm_x4(smb + KV_AHI + apos + kb * 32, ah0, ah1, ah2, ah3);
        ldsm_x4(smb + KV_ALO + apos + kb * 32, al0, al1, al2, al3);
        #pragma unroll
        for (int nb = 0; nb < 8; nb++) {
            u32 b0, b1, c0r, c1r;
            ldsm_x2(smb + KV_BHI + bpos + nb * (8 * SMSTRIDE) + kb * 32, b0, b1);
            mma16816(acc[nb], ah0, ah1, ah2, ah3, b0, b1);
            mma16816(acc[nb], al0, al1, al2, al3, b0, b1);
            ldsm_x2(smb + KV_BLO + bpos + nb * (8 * SMSTRIDE) + kb * 32, c0r, c1r);
            mma16816(acc[nb], ah0, ah1, ah2, ah3, c0r, c1r);
        }
    }

    const int rA = wid * 16 + (lane >> 2), rB = rA + 8;
    #pragma unroll
    for (int nb = 0; nb < 8; nb++) {
        int col = nb * 8 + (lane & 3) * 2;
        float v0 = acc[nb][0], v1 = acc[nb][1];
        float v2 = acc[nb][2], v3 = acc[nb][3];
        float h0 = bfhi(v0), h1 = bfhi(v1), h2 = bfhi(v2), h3 = bfhi(v3);
        const int ch = c0 + col;
        const size_t iA = ((size_t)(s * M_SEQ + t0 + rA)) * INNER + ch;
        const size_t iB = ((size_t)(s * M_SEQ + t0 + rB)) * INNER + ch;
        *(u32*)&ohi[iA] = pack_bf16(h0, h1);
        *(u32*)&olo[iA] = pack_bf16(v0 - h0, v1 - h1);
        *(u32*)&ohi[iB] = pack_bf16(h2, h3);
        *(u32*)&olo[iB] = pack_bf16(v2 - h2, v3 - h3);
    }
}

// ================= Kernel 4: flash attention (Bc=64, 128 rows, cp.async) =======
// Buffer layout (stride 144, 64 rows each): KHI 0, KLO 9216, VHI 18432, VLO 27648
#define AKHI 0
#define AKLO 9216
#define AVHI 18432
#define AVLO 27648
#define ABUF 36864
#define AQLO 18432      // Q-lo staging base (pre-loop only; aliases buffer 0 V region)

__global__ __launch_bounds__(256) void attn_kernel()
{
    extern __shared__ __align__(16) char sm[];
    const int i0 = blockIdx.x * 128;
    const int h  = blockIdx.y;
    const int s  = blockIdx.z;
    const int tid = threadIdx.x;
    const int lane = tid & 31;
    const int wid = tid >> 5;
    const u32 smb = smem_u32(sm);

    // ---- stage Q (scaled, bf16 split): hi at 0, lo at AQLO ----
    {
        const float* qbase = g_qT + (size_t)i0 * DIMC + h * 64;
        for (int idx = tid; idx < 4096; idx += 256) {
            int r = idx >> 5, c2 = idx & 31;
            const float* qp = qbase + (size_t)r * DIMC + 2 * c2;
            float a = qp[0] * QSCL, b = qp[1] * QSCL;
            float ah = bfhi(a), bh = bfhi(b);
            *(u32*)(sm + r * SMSTRIDE + c2 * 4)        = pack_bf16(ah, bh);
            *(u32*)(sm + AQLO + r * SMSTRIDE + c2 * 4) = pack_bf16(a - ah, b - bh);
        }
    }
    __syncthreads();

    u32 qh[4][4], ql[4][4];
    {
        int qrow = wid * 16 + (lane & 7) + ((lane >> 3) & 1) * 8;
        u32 qoff = smb + qrow * SMSTRIDE + ((lane >> 4) & 1) * 16;
        #pragma unroll
        for (int kb = 0; kb < 4; kb++) {
            ldsm_x4(qoff + kb * 32, qh[kb][0], qh[kb][1], qh[kb][2], qh[kb][3]);
            ldsm_x4(qoff + AQLO + kb * 32, ql[kb][0], ql[kb][1], ql[kb][2], ql[kb][3]);
        }
    }
    __syncthreads();   // Q frags in regs; smem free for K/V buffers

    const __nv_bfloat16* khb = g_khi + (size_t)s * M_SEQ * INNER + h * 64;
    const __nv_bfloat16* klb = g_klo + (size_t)s * M_SEQ * INNER + h * 64;
    const __nv_bfloat16* vhb = g_vhi + (size_t)s * M_SEQ * INNER + h * 64;
    const __nv_bfloat16* vlb = g_vlo + (size_t)s * M_SEQ * INNER + h * 64;

    const u32 lpK = (lane & 7) * SMSTRIDE + ((lane >> 3) & 1) * 16;
    const u32 lpV = (lane & 7) * SMSTRIDE + ((lane >> 3) & 1) * (8 * SMSTRIDE);

    float oacc[8][4];
    #pragma unroll
    for (int nd = 0; nd < 8; nd++)
        #pragma unroll
        for (int u = 0; u < 4; u++) oacc[nd][u] = 0.f;
    float mA = -1e30f, mB = -1e30f, lA = 0.f, lB = 0.f;

    // staging: 64 rows x 8 segs of 16B per array; 2 slots per thread per array
    // prologue: issue tile 0 into buffer 0
    #pragma unroll
    for (int it = 0; it < 2; it++) {
        int slot = tid + it * 256;
        int r = slot >> 3, seg = slot & 7;
        size_t go = (size_t)r * INNER + seg * 8;
        u32 so = smb + r * SMSTRIDE + seg * 16;
        cp_async16(so + AKHI, khb + go);
        cp_async16(so + AKLO, klb + go);
        cp_async16(so + AVHI, vhb + go);
        cp_async16(so + AVLO, vlb + go);
    }
    CP_COMMIT();

    for (int t = 0; t < 16; t++) {
        if (t + 1 < 16) {
            u32 bn = smb + ((t + 1) & 1) * ABUF;
            #pragma unroll
            for (int it = 0; it < 2; it++) {
                int slot = tid + it * 256;
                int r = slot >> 3, seg = slot & 7;
                size_t go = (size_t)((t + 1) * 64 + r) * INNER + seg * 8;
                u32 so = bn + r * SMSTRIDE + seg * 16;
                cp_async16(so + AKHI, khb + go);
                cp_async16(so + AKLO, klb + go);
                cp_async16(so + AVHI, vhb + go);
                cp_async16(so + AVLO, vlb + go);
            }
            CP_COMMIT();
            CP_WAIT(1);
        } else {
            CP_WAIT(0);
        }
        __syncthreads();
        const u32 bb = smb + (t & 1) * ABUF;

        // ---- S = Q K^T (hh + lh + hl), 64 keys ----
        float sacc[8][4];
        #pragma unroll
        for (int nb = 0; nb < 8; nb++)
            #pragma unroll
            for (int u = 0; u < 4; u++) sacc[nb][u] = 0.f;
        #pragma unroll
        for (int kb = 0; kb < 4; kb++) {
            #pragma unroll
            for (int nb = 0; nb < 8; nb++) {
                u32 b0, b1, c0, c1;
                ldsm_x2(bb + AKHI + lpK + nb * (8 * SMSTRIDE) + kb * 32, b0, b1);
                mma16816(sacc[nb], qh[kb][0], qh[kb][1], qh[kb][2], qh[kb][3], b0, b1);
                mma16816(sacc[nb], ql[kb][0], ql[kb][1], ql[kb][2], ql[kb][3], b0, b1);
                ldsm_x2(bb + AKLO + lpK + nb * (8 * SMSTRIDE) + kb * 32, c0, c1);
                mma16816(sacc[nb], qh[kb][0], qh[kb][1], qh[kb][2], qh[kb][3], c0, c1);
            }
        }

        // ---- online softmax (base-2) ----
        float tA = -1e30f, tB = -1e30f;
        #pragma unroll
        for (int nb = 0; nb < 8; nb++) {
            tA = fmaxf(tA, fmaxf(sacc[nb][0], sacc[nb][1]));
            tB = fmaxf(tB, fmaxf(sacc[nb][2], sacc[nb][3]));
        }
        tA = fmaxf(tA, __shfl_xor_sync(0xffffffffu, tA, 1));
        tA = fmaxf(tA, __shfl_xor_sync(0xffffffffu, tA, 2));
        tB = fmaxf(tB, __shfl_xor_sync(0xffffffffu, tB, 1));
        tB = fmaxf(tB, __shfl_xor_sync(0xffffffffu, tB, 2));
        float mAn = fmaxf(mA, tA), mBn = fmaxf(mB, tB);
        float cA = ex2f(mA - mAn), cB = ex2f(mB - mBn);
        mA = mAn; mB = mBn;
        float sA = 0.f, sB = 0.f;
        #pragma unroll
        for (int nb = 0; nb < 8; nb++) {
            sacc[nb][0] = ex2f(sacc[nb][0] - mAn);
            sacc[nb][1] = ex2f(sacc[nb][1] - mAn);
            sacc[nb][2] = ex2f(sacc[nb][2] - mBn);
            sacc[nb][3] = ex2f(sacc[nb][3] - mBn);
            sA += sacc[nb][0] + sacc[nb][1];
            sB += sacc[nb][2] + sacc[nb][3];
        }
        sA += __shfl_xor_sync(0xffffffffu, sA, 1);
        sA += __shfl_xor_sync(0xffffffffu, sA, 2);
        sB += __shfl_xor_sync(0xffffffffu, sB, 1);
        sB += __shfl_xor_sync(0xffffffffu, sB, 2);
        lA = lA * cA + sA;
        lB = lB * cB + sB;
        #pragma unroll
        for (int nd = 0; nd < 8; nd++) {
            oacc[nd][0] *= cA; oacc[nd][1] *= cA;
            oacc[nd][2] *= cB; oacc[nd][3] *= cB;
        }

        // ---- O += P V (ph*vh + pl*vh + ph*vl), 4 k-blocks of 16 keys ----
        #pragma unroll
        for (int kb = 0; kb < 4; kb++) {
            const float* pL = sacc[2 * kb];
            const float* pH = sacc[2 * kb + 1];
            float h00 = bfhi(pL[0]), h01 = bfhi(pL[1]), h02 = bfhi(pL[2]), h03 = bfhi(pL[3]);
            float h10 = bfhi(pH[0]), h11 = bfhi(pH[1]), h12 = bfhi(pH[2]), h13 = bfhi(pH[3]);
            u32 a0 = pack_bf16(h00, h01), a1 = pack_bf16(h02, h03);
            u32 a2 = pack_bf16(h10, h11), a3 = pack_bf16(h12, h13);
            u32 e0 = pack_bf16(pL[0] - h00, pL[1] - h01);
            u32 e1 = pack_bf16(pL[2] - h02, pL[3] - h03);
            u32 e2 = pack_bf16(pH[0] - h10, pH[1] - h11);
            u32 e3 = pack_bf16(pH[2] - h12, pH[3] - h13);
            #pragma unroll
            for (int nd = 0; nd < 8; nd++) {
                u32 b0, b1, c0, c1;
                ldsm_x2_t(bb + AVHI + lpV + kb * (16 * SMSTRIDE) + nd * 16, b0, b1);
                mma16816(oacc[nd], a0, a1, a2, a3, b0, b1);
                mma16816(oacc[nd], e0, e1, e2, e3, b0, b1);
                ldsm_x2_t(bb + AVLO + lpV + kb * (16 * SMSTRIDE) + nd * 16, c0, c1);
                mma16816(oacc[nd], a0, a1, a2, a3, c0, c1);
            }
        }
        __syncthreads();   // buffer consumed; safe for next issue
    }

    // ---- epilogue: normalize, store to g_att[s][i][c] ----
    float invA = 1.f / lA, invB = 1.f / lB;
    const int rA = wid * 16 + (lane >> 2), rB = rA + 8;
    float* oA = g_att + (size_t)s * N_SEQ * INNER + (size_t)(i0 + rA) * INNER + h * 64;
    float* oB = g_att + (size_t)s * N_SEQ * INNER + (size_t)(i0 + rB) * INNER + h * 64;
    #pragma unroll
    for (int nd = 0; nd < 8; nd++) {
        int col = nd * 8 + (lane & 3) * 2;
        *(float2*)&oA[col] = make_float2(oacc[nd][0] * invA, oacc[nd][1] * invA);
        *(float2*)&oB[col] = make_float2(oacc[nd][2] * invB, oacc[nd][3] * invB);
    }
}

// ================= Kernel 5: stream-mean + Wo GEMM (warp-MMA) ==================
__global__ __launch_bounds__(128) void outproj_mma_kernel(
    const float* __restrict__ Wo, const float* __restrict__ bo,
    float* __restrict__ out)
{
    __shared__ __align__(16) char sm[36864];
    const int i0 = blockIdx.x * 64;
    const int d0 = blockIdx.y * 64;
    const int tid = threadIdx.x;
    const int lane = tid & 31, wid = tid >> 5;
    const u32 smb = smem_u32(sm);

    float acc[8][4];
    #pragma unroll
    for (int nb = 0; nb < 8; nb++)
        #pragma unroll
        for (int u = 0; u < 4; u++) acc[nb][u] = 0.f;

    const u32 apos = (wid * 16 + (lane & 7) + ((lane >> 3) & 1) * 8) * SMSTRIDE
                   + ((lane >> 4) & 1) * 16;
    const u32 bpos = (lane & 7) * SMSTRIDE + ((lane >> 3) & 1) * 16;

    for (int k0 = 0; k0 < 512; k0 += 64) {
        __syncthreads();
        for (int idx = tid; idx < 2048; idx += 128) {
            int r = idx >> 5, c2 = idx & 31;
            const float* a0p = &g_att[(size_t)(i0 + r) * INNER + k0 + 2 * c2];
            float2 u0 = *(const float2*)a0p;
            float2 u1 = *(const float2*)(a0p + (size_t)N_SEQ * INNER);
            float ax = 0.5f * (u0.x + u1.x), ay = 0.5f * (u0.y + u1.y);
            float ah = bfhi(ax), bh = bfhi(ay);
            u32 so = r * SMSTRIDE + c2 * 4;
            *(u32*)(sm + OP_AHI + so) = pack_bf16(ah, bh);
            *(u32*)(sm + OP_ALO + so) = pack_bf16(ax - ah, ay - bh);
            float2 w = *(const float2*)&Wo[(d0 + r) * INNER + k0 + 2 * c2];
            float wh = bfhi(w.x), xh = bfhi(w.y);
            *(u32*)(sm + OP_BHI + so) = pack_bf16(wh, xh);
            *(u32*)(sm + OP_BLO + so) = pack_bf16(w.x - wh, w.y - xh);
        }
        __syncthreads();

        #pragma unroll
        for (int kb = 0; kb < 4; kb++) {
            u32 ah0, ah1, ah2, ah3, al0, al1, al2, al3;
            ldsm_x4(smb + OP_AHI + apos + kb * 32, ah0, ah1, ah2, ah3);
            ldsm_x4(smb + OP_ALO + apos + kb * 32, al0, al1, al2, al3);
            #pragma unroll
            for (int nb = 0; nb < 8; nb++) {
                u32 b0, b1, c0r, c1r;
                ldsm_x2(smb + OP_BHI + bpos + nb * (8 * SMSTRIDE) + kb * 32, b0, b1);
                mma16816(acc[nb], ah0, ah1, ah2, ah3, b0, b1);
                mma16816(acc[nb], al0, al1, al2, al3, b0, b1);
                ldsm_x2(smb + OP_BLO + bpos + nb * (8 * SMSTRIDE) + kb * 32, c0r, c1r);
                mma16816(acc[nb], ah0, ah1, ah2, ah3, c0r, c1r);
            }
        }
    }

    const int rA = wid * 16 + (lane >> 2), rB = rA + 8;
    #pragma unroll
    for (int nb = 0; nb < 8; nb++) {
        int col = nb * 8 + (lane & 3) * 2;
        float b0 = bo[d0 + col], b1 = bo[d0 + col + 1];
        *(float2*)&out[(size_t)(i0 + rA) * DIMC + d0 + col] =
            make_float2(acc[nb][0] + b0, acc[nb][1] + b1);
        *(float2*)&out[(size_t)(i0 + rB) * DIMC + d0 + col] =
            make_float2(acc[nb][2] + b0, acc[nb][3] + b1);
    }
}

// ================= launch ======================================================
extern "C" void kernel_launch(void* const* d_in, const int* in_sizes, int n_in,
                              void* d_out, int out_size)
{
    const float* x   = (const float*)d_in[0];
    const float* px  = (const float*)d_in[1];
    const float* Wq  = (const float*)d_in[2];
    const float* Wk  = (const float*)d_in[3];
    const float* Wv  = (const float*)d_in[4];
    const float* Wo  = (const float*)d_in[5];
    const float* bo  = (const float*)d_in[6];
    const float* Wdw = (const float*)d_in[7];
    const float* bdw = (const float*)d_in[8];
    const float* Wp  = (const float*)d_in[9];
    float* out = (float*)d_out;

    cudaFuncSetAttribute(attn_kernel,
                         cudaFuncAttributeMaxDynamicSharedMemorySize, 2 * ABUF);

    qproj_mma_kernel<<<dim3(64, 8), 128>>>(x, px, Wq);
    offset_kernel<<<dim3(8, 8), 128>>>(Wdw, bdw, Wp);
    kvproj_mma_kernel<<<dim3(16, 8, 4), 128>>>(x, px, Wk, Wv);
    attn_kernel<<<dim3(32, HEADS, 2), 256, 2 * ABUF>>>();
    outproj_mma_kernel<<<dim3(64, 8), 128>>>(Wo, bo, out);
}

// round 12
// speedup vs baseline: 2.0711x; 1.1686x over previous
#include <cuda_runtime.h>
#include <cuda_bf16.h>
#include <math.h>

typedef unsigned int u32;
typedef unsigned short u16;
typedef unsigned char u8;
typedef unsigned long long u64;
typedef unsigned long long ull;

#define N_SEQ 4096
#define M_SEQ 1024
#define DIMC  512
#define INNER 512
#define HEADS 8
#define GROUPS 8

// ---------------- warp-MMA helpers -------------------------------------------
__device__ __forceinline__ u32 smem_u32(const void* p) {
    u32 a;
    asm("{ .reg .u64 t; cvta.to.shared.u64 t, %1; cvt.u32.u64 %0, t; }" : "=r"(a) : "l"(p));
    return a;
}
__device__ __forceinline__ float ex2f(float x) {
    float r; asm("ex2.approx.ftz.f32 %0, %1;" : "=f"(r) : "f"(x)); return r;
}
__device__ __forceinline__ void ldsm_x4(u32 addr, u32& r0, u32& r1, u32& r2, u32& r3) {
    asm volatile("ldmatrix.sync.aligned.m8n8.x4.shared.b16 {%0,%1,%2,%3}, [%4];"
        : "=r"(r0), "=r"(r1), "=r"(r2), "=r"(r3) : "r"(addr));
}
__device__ __forceinline__ void ldsm_x2(u32 addr, u32& r0, u32& r1) {
    asm volatile("ldmatrix.sync.aligned.m8n8.x2.shared.b16 {%0,%1}, [%2];"
        : "=r"(r0), "=r"(r1) : "r"(addr));
}
__device__ __forceinline__ void ldsm_x2_t(u32 addr, u32& r0, u32& r1) {
    asm volatile("ldmatrix.sync.aligned.m8n8.x2.trans.shared.b16 {%0,%1}, [%2];"
        : "=r"(r0), "=r"(r1) : "r"(addr));
}
__device__ __forceinline__ void mma16816(float* c, u32 a0, u32 a1, u32 a2, u32 a3,
                                         u32 b0, u32 b1) {
    asm volatile(
        "mma.sync.aligned.m16n8k16.row.col.f32.bf16.bf16.f32 "
        "{%0,%1,%2,%3}, {%4,%5,%6,%7}, {%8,%9}, {%0,%1,%2,%3};"
        : "+f"(c[0]), "+f"(c[1]), "+f"(c[2]), "+f"(c[3])
        : "r"(a0), "r"(a1), "r"(a2), "r"(a3), "r"(b0), "r"(b1));
}
__device__ __forceinline__ u32 pack_bf16(float a, float b) {
    return ((u32)__bfloat16_as_ushort(__float2bfloat16(b)) << 16) |
           (u32)__bfloat16_as_ushort(__float2bfloat16(a));
}
__device__ __forceinline__ float bfhi(float x) {
    return __bfloat162float(__float2bfloat16(x));
}
__device__ __forceinline__ void cp_async16(u32 s, const void* g) {
    asm volatile("cp.async.cg.shared.global [%0], [%1], 16;" :: "r"(s), "l"(g));
}
#define CP_COMMIT() asm volatile("cp.async.commit_group;" ::: "memory")
#define CP_WAIT(n)  asm volatile("cp.async.wait_group %0;" :: "n"(n) : "memory")

// ---------------- scratch (static device globals) ------------------------------
__device__ float g_qT[N_SEQ * DIMC];                 // q[i][c]
__device__ float g_pos[GROUPS * M_SEQ];
__device__ __nv_bfloat16 g_khi[2 * M_SEQ * INNER];   // k hi  [s][t][c]
__device__ __nv_bfloat16 g_klo[2 * M_SEQ * INNER];   // k lo
__device__ __nv_bfloat16 g_vhi[2 * M_SEQ * INNER];   // v hi  [s][t][c]
__device__ __nv_bfloat16 g_vlo[2 * M_SEQ * INNER];   // v lo
__device__ float g_att[2 * N_SEQ * INNER];           // attn out [s][i][c]

#define SMSTRIDE 144
#define QSCL 0.1803368801111204f   // 0.125 * log2(e)

// ================= Kernel 1: q projection via warp-MMA =========================
#define OP_AHI 0
#define OP_ALO 9216
#define OP_BHI 18432
#define OP_BLO 27648

__global__ __launch_bounds__(128) void qproj_mma_kernel(
    const float* __restrict__ x, const float* __restrict__ px,
    const float* __restrict__ Wq)
{
    __shared__ __align__(16) char sm[36864];
    const int i0 = blockIdx.x * 64;
    const int g  = blockIdx.y;
    const int c0 = g * 64;
    const float* src = (g < 4) ? px : x;
    const int   base = (g & 3) * 128;
    const int tid = threadIdx.x;
    const int lane = tid & 31, wid = tid >> 5;
    const u32 smb = smem_u32(sm);

    float acc[8][4];
    #pragma unroll
    for (int nb = 0; nb < 8; nb++)
        #pragma unroll
        for (int u = 0; u < 4; u++) acc[nb][u] = 0.f;

    const u32 apos = (wid * 16 + (lane & 7) + ((lane >> 3) & 1) * 8) * SMSTRIDE
                   + ((lane >> 4) & 1) * 16;
    const u32 bpos = (lane & 7) * SMSTRIDE + ((lane >> 3) & 1) * 16;

    for (int k0 = 0; k0 < 128; k0 += 64) {
        __syncthreads();
        for (int idx = tid; idx < 2048; idx += 128) {
            int r = idx >> 5, c2 = idx & 31;
            float2 a = *(const float2*)&src[(size_t)(i0 + r) * DIMC + base + k0 + 2 * c2];
            float ah = bfhi(a.x), bh = bfhi(a.y);
            u32 so = r * SMSTRIDE + c2 * 4;
            *(u32*)(sm + OP_AHI + so) = pack_bf16(ah, bh);
            *(u32*)(sm + OP_ALO + so) = pack_bf16(a.x - ah, a.y - bh);
            float2 w = *(const float2*)&Wq[(c0 + r) * 128 + k0 + 2 * c2];
            float wh = bfhi(w.x), xh = bfhi(w.y);
            *(u32*)(sm + OP_BHI + so) = pack_bf16(wh, xh);
            *(u32*)(sm + OP_BLO + so) = pack_bf16(w.x - wh, w.y - xh);
        }
        __syncthreads();
        #pragma unroll
        for (int kb = 0; kb < 4; kb++) {
            u32 ah0, ah1, ah2, ah3, al0, al1, al2, al3;
            ldsm_x4(smb + OP_AHI + apos + kb * 32, ah0, ah1, ah2, ah3);
            ldsm_x4(smb + OP_ALO + apos + kb * 32, al0, al1, al2, al3);
            #pragma unroll
            for (int nb = 0; nb < 8; nb++) {
                u32 b0, b1, c0r, c1r;
                ldsm_x2(smb + OP_BHI + bpos + nb * (8 * SMSTRIDE) + kb * 32, b0, b1);
                mma16816(acc[nb], ah0, ah1, ah2, ah3, b0, b1);
                mma16816(acc[nb], al0, al1, al2, al3, b0, b1);
                ldsm_x2(smb + OP_BLO + bpos + nb * (8 * SMSTRIDE) + kb * 32, c0r, c1r);
                mma16816(acc[nb], ah0, ah1, ah2, ah3, c0r, c1r);
            }
        }
    }
    const int rA = wid * 16 + (lane >> 2), rB = rA + 8;
    #pragma unroll
    for (int nb = 0; nb < 8; nb++) {
        int col = nb * 8 + (lane & 3) * 2;
        *(float2*)&g_qT[(size_t)(i0 + rA) * DIMC + c0 + col] =
            make_float2(acc[nb][0], acc[nb][1]);
        *(float2*)&g_qT[(size_t)(i0 + rB) * DIMC + c0 + col] =
            make_float2(acc[nb][2], acc[nb][3]);
    }
}

// ================= Kernel 2: offset network ====================================
__global__ __launch_bounds__(128) void offset_kernel(
    const float* __restrict__ Wdw, const float* __restrict__ bdw,
    const float* __restrict__ Wp)
{
    const int g = blockIdx.y;
    const int t = blockIdx.x * 128 + threadIdx.x;
    const int pbase = 4 * t - 1;
    float s = 0.f;
    for (int c = 0; c < 64; c++) {
        float hv = bdw[c];
        #pragma unroll
        for (int k = 0; k < 6; k++) {
            int p = pbase + k;
            if (p >= 0 && p < N_SEQ) hv += Wdw[c * 6 + k] * g_qT[(size_t)p * DIMC + g * 64 + c];
        }
        hv = 0.5f * hv * (1.f + erff(hv * 0.7071067811865476f));
        s += Wp[c] * hv;
    }
    float off = tanhf(s) * 4.0f;
    float vg  = 2.0f * ((float)t + off) / 1023.0f - 1.0f;
    float pos = ((vg + 1.0f) * (float)N_SEQ - 1.0f) * 0.5f;
    g_pos[g * M_SEQ + t] = pos;
}

// ================= Kernel 3: fused gridsample + k/v projection =================
#define KV_AHI 0
#define KV_ALO 9216
#define KV_BHI 18432
#define KV_BLO 27648

__global__ __launch_bounds__(128) void kvproj_mma_kernel(
    const float* __restrict__ x, const float* __restrict__ px,
    const float* __restrict__ Wk, const float* __restrict__ Wv)
{
    __shared__ __align__(16) char sm[36864];
    const int t0 = blockIdx.x * 64;
    const int g  = blockIdx.y;
    const int s  = blockIdx.z & 1;
    const int which = blockIdx.z >> 1;
    const int c0 = g * 64;
    const float* W = which ? Wv : Wk;
    const float* src = (s == 0) ? px : x;
    __nv_bfloat16* ohi = which ? g_vhi : g_khi;
    __nv_bfloat16* olo = which ? g_vlo : g_klo;
    const int tid = threadIdx.x;
    const int lane = tid & 31, wid = tid >> 5;
    const u32 smb = smem_u32(sm);

    for (int idx = tid; idx < 2048; idx += 128) {
        int r = idx >> 5, c2 = idx & 31;
        const float pos = g_pos[g * M_SEQ + t0 + r];
        const float x0f = floorf(pos);
        const float w1 = pos - x0f;
        const int p0 = (int)x0f;
        const int ch = c0 + 2 * c2;
        float ax = 0.f, ay = 0.f;
        if (p0 >= 0 && p0 < N_SEQ) {
            float2 f = *(const float2*)&src[(size_t)p0 * DIMC + ch];
            ax += (1.f - w1) * f.x; ay += (1.f - w1) * f.y;
        }
        if (p0 + 1 >= 0 && p0 + 1 < N_SEQ) {
            float2 f = *(const float2*)&src[(size_t)(p0 + 1) * DIMC + ch];
            ax += w1 * f.x; ay += w1 * f.y;
        }
        float ah = bfhi(ax), bh = bfhi(ay);
        u32 so = r * SMSTRIDE + c2 * 4;
        *(u32*)(sm + KV_AHI + so) = pack_bf16(ah, bh);
        *(u32*)(sm + KV_ALO + so) = pack_bf16(ax - ah, ay - bh);
        float2 w = *(const float2*)&W[(c0 + r) * 64 + 2 * c2];
        float wh = bfhi(w.x), xh = bfhi(w.y);
        *(u32*)(sm + KV_BHI + so) = pack_bf16(wh, xh);
        *(u32*)(sm + KV_BLO + so) = pack_bf16(w.x - wh, w.y - xh);
    }
    __syncthreads();

    float acc[8][4];
    #pragma unroll
    for (int nb = 0; nb < 8; nb++)
        #pragma unroll
        for (int u = 0; u < 4; u++) acc[nb][u] = 0.f;

    const u32 apos = (wid * 16 + (lane & 7) + ((lane >> 3) & 1) * 8) * SMSTRIDE
                   + ((lane >> 4) & 1) * 16;
    const u32 bpos = (lane & 7) * SMSTRIDE + ((lane >> 3) & 1) * 16;

    #pragma unroll
    for (int kb = 0; kb < 4; kb++) {
        u32 ah0, ah1, ah2, ah3, al0, al1, al2, al3;
        ldsm_x4(smb + KV_AHI + apos + kb * 32, ah0, ah1, ah2, ah3);
        ldsm_x4(smb + KV_ALO + apos + kb * 32, al0, al1, al2, al3);
        #pragma unroll
        for (int nb = 0; nb < 8; nb++) {
            u32 b0, b1, c0r, c1r;
            ldsm_x2(smb + KV_BHI + bpos + nb * (8 * SMSTRIDE) + kb * 32, b0, b1);
            mma16816(acc[nb], ah0, ah1, ah2, ah3, b0, b1);
            mma16816(acc[nb], al0, al1, al2, al3, b0, b1);
            ldsm_x2(smb + KV_BLO + bpos + nb * (8 * SMSTRIDE) + kb * 32, c0r, c1r);
            mma16816(acc[nb], ah0, ah1, ah2, ah3, c0r, c1r);
        }
    }

    const int rA = wid * 16 + (lane >> 2), rB = rA + 8;
    #pragma unroll
    for (int nb = 0; nb < 8; nb++) {
        int col = nb * 8 + (lane & 3) * 2;
        float v0 = acc[nb][0], v1 = acc[nb][1];
        float v2 = acc[nb][2], v3 = acc[nb][3];
        float h0 = bfhi(v0), h1 = bfhi(v1), h2 = bfhi(v2), h3 = bfhi(v3);
        const int ch = c0 + col;
        const size_t iA = ((size_t)(s * M_SEQ + t0 + rA)) * INNER + ch;
        const size_t iB = ((size_t)(s * M_SEQ + t0 + rB)) * INNER + ch;
        *(u32*)&ohi[iA] = pack_bf16(h0, h1);
        *(u32*)&olo[iA] = pack_bf16(v0 - h0, v1 - h1);
        *(u32*)&ohi[iB] = pack_bf16(h2, h3);
        *(u32*)&olo[iB] = pack_bf16(v2 - h2, v3 - h3);
    }
}

// ================= Kernel 4: flash attention (Bc=64, Q-in-smem, 2 CTA/SM) ======
// Dynamic smem: QHI 0, QLO 18432, buf0 36864, buf1 73728 -> 110592 total
#define AQHI 0
#define AQLO 18432
#define ABASE 36864
#define AKHI 0
#define AKLO 9216
#define AVHI 18432
#define AVLO 27648
#define ABUF 36864

__global__ __launch_bounds__(256, 2) void attn_kernel()
{
    extern __shared__ __align__(16) char sm[];
    const int i0 = blockIdx.x * 128;
    const int h  = blockIdx.y;
    const int s  = blockIdx.z;
    const int tid = threadIdx.x;
    const int lane = tid & 31;
    const int wid = tid >> 5;
    const u32 smb = smem_u32(sm);

    // ---- stage Q (scaled, bf16 split) into persistent strip ----
    {
        const float* qbase = g_qT + (size_t)i0 * DIMC + h * 64;
        for (int idx = tid; idx < 4096; idx += 256) {
            int r = idx >> 5, c2 = idx & 31;
            const float* qp = qbase + (size_t)r * DIMC + 2 * c2;
            float a = qp[0] * QSCL, b = qp[1] * QSCL;
            float ah = bfhi(a), bh = bfhi(b);
            *(u32*)(sm + AQHI + r * SMSTRIDE + c2 * 4) = pack_bf16(ah, bh);
            *(u32*)(sm + AQLO + r * SMSTRIDE + c2 * 4) = pack_bf16(a - ah, b - bh);
        }
    }

    const __nv_bfloat16* khb = g_khi + (size_t)s * M_SEQ * INNER + h * 64;
    const __nv_bfloat16* klb = g_klo + (size_t)s * M_SEQ * INNER + h * 64;
    const __nv_bfloat16* vhb = g_vhi + (size_t)s * M_SEQ * INNER + h * 64;
    const __nv_bfloat16* vlb = g_vlo + (size_t)s * M_SEQ * INNER + h * 64;

    const u32 lpK = (lane & 7) * SMSTRIDE + ((lane >> 3) & 1) * 16;
    const u32 lpV = (lane & 7) * SMSTRIDE + ((lane >> 3) & 1) * (8 * SMSTRIDE);
    const u32 qfoff = smb + (wid * 16 + (lane & 7) + ((lane >> 3) & 1) * 8) * SMSTRIDE
                    + ((lane >> 4) & 1) * 16;

    float oacc[8][4];
    #pragma unroll
    for (int nd = 0; nd < 8; nd++)
        #pragma unroll
        for (int u = 0; u < 4; u++) oacc[nd][u] = 0.f;
    float mA = -1e30f, mB = -1e30f, lA = 0.f, lB = 0.f;

    // prologue: issue tile 0 into buffer 0
    #pragma unroll
    for (int it = 0; it < 2; it++) {
        int slot = tid + it * 256;
        int r = slot >> 3, seg = slot & 7;
        size_t go = (size_t)r * INNER + seg * 8;
        u32 so = smb + ABASE + r * SMSTRIDE + seg * 16;
        cp_async16(so + AKHI, khb + go);
        cp_async16(so + AKLO, klb + go);
        cp_async16(so + AVHI, vhb + go);
        cp_async16(so + AVLO, vlb + go);
    }
    CP_COMMIT();

    for (int t = 0; t < 16; t++) {
        if (t + 1 < 16) {
            u32 bn = smb + ABASE + ((t + 1) & 1) * ABUF;
            #pragma unroll
            for (int it = 0; it < 2; it++) {
                int slot = tid + it * 256;
                int r = slot >> 3, seg = slot & 7;
                size_t go = (size_t)((t + 1) * 64 + r) * INNER + seg * 8;
                u32 so = bn + r * SMSTRIDE + seg * 16;
                cp_async16(so + AKHI, khb + go);
                cp_async16(so + AKLO, klb + go);
                cp_async16(so + AVHI, vhb + go);
                cp_async16(so + AVLO, vlb + go);
            }
            CP_COMMIT();
            CP_WAIT(1);
        } else {
            CP_WAIT(0);
        }
        __syncthreads();
        const u32 bb = smb + ABASE + (t & 1) * ABUF;

        // ---- S = Q K^T (hh + lh + hl), 64 keys; Q frags loaded per-kb ----
        float sacc[8][4];
        #pragma unroll
        for (int nb = 0; nb < 8; nb++)
            #pragma unroll
            for (int u = 0; u < 4; u++) sacc[nb][u] = 0.f;
        #pragma unroll
        for (int kb = 0; kb < 4; kb++) {
            u32 q0, q1, q2, q3, l0, l1, l2, l3;
            ldsm_x4(qfoff + AQHI + kb * 32, q0, q1, q2, q3);
            ldsm_x4(qfoff + AQLO + kb * 32, l0, l1, l2, l3);
            #pragma unroll
            for (int nb = 0; nb < 8; nb++) {
                u32 b0, b1, c0, c1;
                ldsm_x2(bb + AKHI + lpK + nb * (8 * SMSTRIDE) + kb * 32, b0, b1);
                mma16816(sacc[nb], q0, q1, q2, q3, b0, b1);
                mma16816(sacc[nb], l0, l1, l2, l3, b0, b1);
                ldsm_x2(bb + AKLO + lpK + nb * (8 * SMSTRIDE) + kb * 32, c0, c1);
                mma16816(sacc[nb], q0, q1, q2, q3, c0, c1);
            }
        }

        // ---- online softmax (base-2) ----
        float tA = -1e30f, tB = -1e30f;
        #pragma unroll
        for (int nb = 0; nb < 8; nb++) {
            tA = fmaxf(tA, fmaxf(sacc[nb][0], sacc[nb][1]));
            tB = fmaxf(tB, fmaxf(sacc[nb][2], sacc[nb][3]));
        }
        tA = fmaxf(tA, __shfl_xor_sync(0xffffffffu, tA, 1));
        tA = fmaxf(tA, __shfl_xor_sync(0xffffffffu, tA, 2));
        tB = fmaxf(tB, __shfl_xor_sync(0xffffffffu, tB, 1));
        tB = fmaxf(tB, __shfl_xor_sync(0xffffffffu, tB, 2));
        float mAn = fmaxf(mA, tA), mBn = fmaxf(mB, tB);
        float cA = ex2f(mA - mAn), cB = ex2f(mB - mBn);
        mA = mAn; mB = mBn;
        float sA = 0.f, sB = 0.f;
        #pragma unroll
        for (int nb = 0; nb < 8; nb++) {
            sacc[nb][0] = ex2f(sacc[nb][0] - mAn);
            sacc[nb][1] = ex2f(sacc[nb][1] - mAn);
            sacc[nb][2] = ex2f(sacc[nb][2] - mBn);
            sacc[nb][3] = ex2f(sacc[nb][3] - mBn);
            sA += sacc[nb][0] + sacc[nb][1];
            sB += sacc[nb][2] + sacc[nb][3];
        }
        sA += __shfl_xor_sync(0xffffffffu, sA, 1);
        sA += __shfl_xor_sync(0xffffffffu, sA, 2);
        sB += __shfl_xor_sync(0xffffffffu, sB, 1);
        sB += __shfl_xor_sync(0xffffffffu, sB, 2);
        lA = lA * cA + sA;
        lB = lB * cB + sB;
        #pragma unroll
        for (int nd = 0; nd < 8; nd++) {
            oacc[nd][0] *= cA; oacc[nd][1] *= cA;
            oacc[nd][2] *= cB; oacc[nd][3] *= cB;
        }

        // ---- O += P V (ph*vh + pl*vh + ph*vl), 4 k-blocks of 16 keys ----
        #pragma unroll
        for (int kb = 0; kb < 4; kb++) {
            const float* pL = sacc[2 * kb];
            const float* pH = sacc[2 * kb + 1];
            float h00 = bfhi(pL[0]), h01 = bfhi(pL[1]), h02 = bfhi(pL[2]), h03 = bfhi(pL[3]);
            float h10 = bfhi(pH[0]), h11 = bfhi(pH[1]), h12 = bfhi(pH[2]), h13 = bfhi(pH[3]);
            u32 a0 = pack_bf16(h00, h01), a1 = pack_bf16(h02, h03);
            u32 a2 = pack_bf16(h10, h11), a3 = pack_bf16(h12, h13);
            u32 e0 = pack_bf16(pL[0] - h00, pL[1] - h01);
            u32 e1 = pack_bf16(pL[2] - h02, pL[3] - h03);
            u32 e2 = pack_bf16(pH[0] - h10, pH[1] - h11);
            u32 e3 = pack_bf16(pH[2] - h12, pH[3] - h13);
            #pragma unroll
            for (int nd = 0; nd < 8; nd++) {
                u32 b0, b1, c0, c1;
                ldsm_x2_t(bb + AVHI + lpV + kb * (16 * SMSTRIDE) + nd * 16, b0, b1);
                mma16816(oacc[nd], a0, a1, a2, a3, b0, b1);
                mma16816(oacc[nd], e0, e1, e2, e3, b0, b1);
                ldsm_x2_t(bb + AVLO + lpV + kb * (16 * SMSTRIDE) + nd * 16, c0, c1);
                mma16816(oacc[nd], a0, a1, a2, a3, c0, c1);
            }
        }
        __syncthreads();   // buffer consumed; safe for next issue
    }

    // ---- epilogue: normalize, store to g_att[s][i][c] ----
    float invA = 1.f / lA, invB = 1.f / lB;
    const int rA = wid * 16 + (lane >> 2), rB = rA + 8;
    float* oA = g_att + (size_t)s * N_SEQ * INNER + (size_t)(i0 + rA) * INNER + h * 64;
    float* oB = g_att + (size_t)s * N_SEQ * INNER + (size_t)(i0 + rB) * INNER + h * 64;
    #pragma unroll
    for (int nd = 0; nd < 8; nd++) {
        int col = nd * 8 + (lane & 3) * 2;
        *(float2*)&oA[col] = make_float2(oacc[nd][0] * invA, oacc[nd][1] * invA);
        *(float2*)&oB[col] = make_float2(oacc[nd][2] * invB, oacc[nd][3] * invB);
    }
}

// ================= Kernel 5: stream-mean + Wo GEMM (warp-MMA) ==================
__global__ __launch_bounds__(128) void outproj_mma_kernel(
    const float* __restrict__ Wo, const float* __restrict__ bo,
    float* __restrict__ out)
{
    __shared__ __align__(16) char sm[36864];
    const int i0 = blockIdx.x * 64;
    const int d0 = blockIdx.y * 64;
    const int tid = threadIdx.x;
    const int lane = tid & 31, wid = tid >> 5;
    const u32 smb = smem_u32(sm);

    float acc[8][4];
    #pragma unroll
    for (int nb = 0; nb < 8; nb++)
        #pragma unroll
        for (int u = 0; u < 4; u++) acc[nb][u] = 0.f;

    const u32 apos = (wid * 16 + (lane & 7) + ((lane >> 3) & 1) * 8) * SMSTRIDE
                   + ((lane >> 4) & 1) * 16;
    const u32 bpos = (lane & 7) * SMSTRIDE + ((lane >> 3) & 1) * 16;

    for (int k0 = 0; k0 < 512; k0 += 64) {
        __syncthreads();
        for (int idx = tid; idx < 2048; idx += 128) {
            int r = idx >> 5, c2 = idx & 31;
            const float* a0p = &g_att[(size_t)(i0 + r) * INNER + k0 + 2 * c2];
            float2 u0 = *(const float2*)a0p;
            float2 u1 = *(const float2*)(a0p + (size_t)N_SEQ * INNER);
            float ax = 0.5f * (u0.x + u1.x), ay = 0.5f * (u0.y + u1.y);
            float ah = bfhi(ax), bh = bfhi(ay);
            u32 so = r * SMSTRIDE + c2 * 4;
            *(u32*)(sm + OP_AHI + so) = pack_bf16(ah, bh);
            *(u32*)(sm + OP_ALO + so) = pack_bf16(ax - ah, ay - bh);
            float2 w = *(const float2*)&Wo[(d0 + r) * INNER + k0 + 2 * c2];
            float wh = bfhi(w.x), xh = bfhi(w.y);
            *(u32*)(sm + OP_BHI + so) = pack_bf16(wh, xh);
            *(u32*)(sm + OP_BLO + so) = pack_bf16(w.x - wh, w.y - xh);
        }
        __syncthreads();

        #pragma unroll
        for (int kb = 0; kb < 4; kb++) {
            u32 ah0, ah1, ah2, ah3, al0, al1, al2, al3;
            ldsm_x4(smb + OP_AHI + apos + kb * 32, ah0, ah1, ah2, ah3);
            ldsm_x4(smb + OP_ALO + apos + kb * 32, al0, al1, al2, al3);
            #pragma unroll
            for (int nb = 0; nb < 8; nb++) {
                u32 b0, b1, c0r, c1r;
                ldsm_x2(smb + OP_BHI + bpos + nb * (8 * SMSTRIDE) + kb * 32, b0, b1);
                mma16816(acc[nb], ah0, ah1, ah2, ah3, b0, b1);
                mma16816(acc[nb], al0, al1, al2, al3, b0, b1);
                ldsm_x2(smb + OP_BLO + bpos + nb * (8 * SMSTRIDE) + kb * 32, c0r, c1r);
                mma16816(acc[nb], ah0, ah1, ah2, ah3, c0r, c1r);
            }
        }
    }

    const int rA = wid * 16 + (lane >> 2), rB = rA + 8;
    #pragma unroll
    for (int nb = 0; nb < 8; nb++) {
        int col = nb * 8 + (lane & 3) * 2;
        float b0 = bo[d0 + col], b1 = bo[d0 + col + 1];
        *(float2*)&out[(size_t)(i0 + rA) * DIMC + d0 + col] =
            make_float2(acc[nb][0] + b0, acc[nb][1] + b1);
        *(float2*)&out[(size_t)(i0 + rB) * DIMC + d0 + col] =
            make_float2(acc[nb][2] + b0, acc[nb][3] + b1);
    }
}

// ================= launch ======================================================
extern "C" void kernel_launch(void* const* d_in, const int* in_sizes, int n_in,
                              void* d_out, int out_size)
{
    const float* x   = (const float*)d_in[0];
    const float* px  = (const float*)d_in[1];
    const float* Wq  = (const float*)d_in[2];
    const float* Wk  = (const float*)d_in[3];
    const float* Wv  = (const float*)d_in[4];
    const float* Wo  = (const float*)d_in[5];
    const float* bo  = (const float*)d_in[6];
    const float* Wdw = (const float*)d_in[7];
    const float* bdw = (const float*)d_in[8];
    const float* Wp  = (const float*)d_in[9];
    float* out = (float*)d_out;

    cudaFuncSetAttribute(attn_kernel,
                         cudaFuncAttributeMaxDynamicSharedMemorySize, ABASE + 2 * ABUF);

    qproj_mma_kernel<<<dim3(64, 8), 128>>>(x, px, Wq);
    offset_kernel<<<dim3(8, 8), 128>>>(Wdw, bdw, Wp);
    kvproj_mma_kernel<<<dim3(16, 8, 4), 128>>>(x, px, Wk, Wv);
    attn_kernel<<<dim3(32, HEADS, 2), 256, ABASE + 2 * ABUF>>>();
    outproj_mma_kernel<<<dim3(64, 8), 128>>>(Wo, bo, out);
}